// round 15
// baseline (speedup 1.0000x reference)
#include <cuda_runtime.h>
#include <cuda_fp16.h>
#include <cstdint>
#include <math.h>

// Problem constants
constexpr int B_ = 2, S_ = 2048, D_ = 1024, H_ = 16, DK_ = 64, DH_ = 4096;
constexpr int M_ROWS = B_ * S_;   // 4096
constexpr float EPS = 1e-5f;
constexpr int SPLITS = 4;

// ---------------------------------------------------------------------------
// Scratch (device globals — no allocation allowed)
// Weights now kept in NATIVE [K,N] layout, fp16.
// ---------------------------------------------------------------------------
__device__ __half g_xh[M_ROWS * D_];
__device__ __half g_qkvh[M_ROWS * D_];
__device__ __half g_atth[M_ROWS * D_];
__device__ __half g_yh[M_ROWS * D_];
__device__ __half g_x1h[M_ROWS * D_];
__device__ __half g_hh[M_ROWS * DH_];
__device__ __half g_parth[SPLITS * M_ROWS * D_];
__device__ __half g_wq[D_ * D_];      // [K=D, N=D]
__device__ __half g_wo[D_ * D_];      // [K=D, N=D]
__device__ __half g_w1[D_ * DH_];     // [K=D, N=DH]
__device__ __half g_w2[DH_ * D_];     // [K=DH, N=D]

// ---------------------------------------------------------------------------
// Low-level helpers
// ---------------------------------------------------------------------------
__device__ __forceinline__ uint32_t smem_to_u32(const void* p) {
    uint32_t a;
    asm("{ .reg .u64 t; cvta.to.shared.u64 t, %1; cvt.u32.u64 %0, t; }"
        : "=r"(a) : "l"(p));
    return a;
}
__device__ __forceinline__ void cpa16(uint32_t d, const void* s) {
    asm volatile("cp.async.cg.shared.global [%0], [%1], 16;" :: "r"(d), "l"(s));
}
#define CP_COMMIT() asm volatile("cp.async.commit_group;" ::: "memory")
#define CP_WAIT1()  asm volatile("cp.async.wait_group 1;" ::: "memory")
#define CP_WAIT0()  asm volatile("cp.async.wait_group 0;" ::: "memory")

__device__ __forceinline__ void ldsm_x4(uint32_t* r, uint32_t addr) {
    asm volatile("ldmatrix.sync.aligned.m8n8.x4.shared.b16 {%0,%1,%2,%3}, [%4];"
        : "=r"(r[0]), "=r"(r[1]), "=r"(r[2]), "=r"(r[3]) : "r"(addr));
}
__device__ __forceinline__ void ldsm_x4t(uint32_t* r, uint32_t addr) {
    asm volatile("ldmatrix.sync.aligned.m8n8.x4.trans.shared.b16 {%0,%1,%2,%3}, [%4];"
        : "=r"(r[0]), "=r"(r[1]), "=r"(r[2]), "=r"(r[3]) : "r"(addr));
}
__device__ __forceinline__ void mma_f16(float* c, const uint32_t* a, const uint32_t* b) {
    asm volatile(
        "mma.sync.aligned.m16n8k16.row.col.f32.f16.f16.f32 "
        "{%0,%1,%2,%3}, {%4,%5,%6,%7}, {%8,%9}, {%0,%1,%2,%3};"
        : "+f"(c[0]), "+f"(c[1]), "+f"(c[2]), "+f"(c[3])
        : "r"(a[0]), "r"(a[1]), "r"(a[2]), "r"(a[3]), "r"(b[0]), "r"(b[1]));
}

#define SWZ128(o) ((o) ^ (((o) >> 3) & 0x70))

__device__ __forceinline__ uint32_t packh(float a, float b) {
    __half2 h = __floats2half2_rn(a, b);
    return *(uint32_t*)&h;
}

// ---------------------------------------------------------------------------
// GEMM tiling: A tile 128x64 K-major (16KB), B tile 64(k) x 128(n) native
// [K,N] layout stored as two 64-col SW128 panels (16KB). Stage 32KB, 3 stages.
// B fragments via ldmatrix.trans (attention-V pattern).
// ---------------------------------------------------------------------------
constexpr int TILE_B  = 16384;
constexpr int STAGE_B = 2 * TILE_B;
constexpr int SMEM_GEMM = 3 * STAGE_B;    // 98304

// Shared inner-loop body: loads A/B frags and issues MMAs for one kblock.
// Bstride = N (native weight row stride).
template <int RELU, int HALFOUT, int SK>
__device__ __forceinline__ void gemm_core(
    const __half* __restrict__ A, const __half* __restrict__ Bw,
    const float* __restrict__ bias, __half* __restrict__ Ch,
    int N, int K_stride_a, long kbase, int NB) {
    extern __shared__ char smem[];
    const uint32_t sb = smem_to_u32(smem);
    const int t = threadIdx.x, lane = t & 31, wid = t >> 5;
    const int wm = wid >> 2, wn = wid & 3;
    const int m0 = blockIdx.y * 128, n0 = blockIdx.x * 128;

    float acc[4][4][4];
#pragma unroll
    for (int i = 0; i < 4; i++)
#pragma unroll
        for (int j = 0; j < 4; j++)
#pragma unroll
            for (int k = 0; k < 4; k++) acc[i][j][k] = 0.f;

    // A loader: 128 rows x 8 chunks; thread -> row t>>1, chunks (t&1)*4..+3
    const int ra = t >> 1, ca = (t & 1) * 4;
    // B loader: 64 k-rows x 16 chunks (256B/row, two 128B panels)
    const int rb = t >> 2, cb0 = (t & 3) * 4;
    auto issue = [&](int kb, int s) {
        const uint32_t st = sb + s * STAGE_B;
        const long ko = kbase + (long)kb * 64;
        const __half* pa = A + (long)(m0 + ra) * K_stride_a + ko;
#pragma unroll
        for (int c = 0; c < 4; c++)
            cpa16(st + SWZ128(ra * 128 + (ca + c) * 16), pa + (ca + c) * 8);
        const __half* pb = Bw + (ko + rb) * (long)N + n0;
#pragma unroll
        for (int c = 0; c < 4; c++) {
            const int cc = cb0 + c;
            const uint32_t d = st + TILE_B + (cc >> 3) * 8192
                             + SWZ128(rb * 128 + (cc & 7) * 16);
            cpa16(d, pb + cc * 8);
        }
    };

    issue(0, 0); CP_COMMIT();
    issue(1, 1); CP_COMMIT();

    for (int kb = 0; kb < NB; kb++) {
        if (kb + 1 < NB) { CP_WAIT1(); } else { CP_WAIT0(); }
        __syncthreads();
        const uint32_t base = sb + (kb % 3) * STAGE_B;
        const uint32_t Ab = base;
        const uint32_t Bpan = base + TILE_B + (wn >> 1) * 8192;
        const uint32_t nbyte = (wn & 1) * 64;
#pragma unroll
        for (int ks = 0; ks < 4; ks++) {
            uint32_t af[4][4];
#pragma unroll
            for (int mt = 0; mt < 4; mt++) {
                const int row = wm * 64 + mt * 16 + (lane & 15);
                const uint32_t off = SWZ128(row * 128 + ks * 32 + (lane >> 4) * 16);
                ldsm_x4(af[mt], Ab + off);
            }
            uint32_t bf[2][4];
#pragma unroll
            for (int ntp = 0; ntp < 2; ntp++) {
                const uint32_t krow = ks * 16 + ((lane >> 3) & 1) * 8 + (lane & 7);
                const uint32_t colb = nbyte + ntp * 32 + (lane >> 4) * 16;
                ldsm_x4t(bf[ntp], Bpan + SWZ128(krow * 128 + colb));
            }
#pragma unroll
            for (int mt = 0; mt < 4; mt++)
#pragma unroll
                for (int ntp = 0; ntp < 2; ntp++) {
                    mma_f16(acc[mt][2 * ntp],     af[mt], bf[ntp]);
                    mma_f16(acc[mt][2 * ntp + 1], af[mt], bf[ntp] + 2);
                }
        }
        if (kb + 2 < NB) { issue(kb + 2, (kb + 2) % 3); CP_COMMIT(); }
    }

    const int g = lane >> 2, tig = lane & 3;
#pragma unroll
    for (int mt = 0; mt < 4; mt++) {
#pragma unroll
        for (int nt = 0; nt < 4; nt++) {
            const int row0 = m0 + wm * 64 + mt * 16 + g;
            const int col  = n0 + wn * 32 + nt * 8 + 2 * tig;
            float v0 = acc[mt][nt][0], v1 = acc[mt][nt][1];
            float v2 = acc[mt][nt][2], v3 = acc[mt][nt][3];
            if (!SK) {
                const float2 bv = *(const float2*)&bias[col];
                v0 += bv.x; v1 += bv.y; v2 += bv.x; v3 += bv.y;
            }
            if (RELU) {
                v0 = fmaxf(v0, 0.f); v1 = fmaxf(v1, 0.f);
                v2 = fmaxf(v2, 0.f); v3 = fmaxf(v3, 0.f);
            }
            *(uint32_t*)&Ch[(long)row0 * N + col]       = packh(v0, v1);
            *(uint32_t*)&Ch[(long)(row0 + 8) * N + col] = packh(v2, v3);
        }
    }
}

template <int RELU>
__global__ __launch_bounds__(256) void mma_gemm(
    const __half* __restrict__ A, const __half* __restrict__ Bw,
    const float* __restrict__ bias, __half* __restrict__ Ch, int N, int K) {
    gemm_core<RELU, 1, 0>(A, Bw, bias, Ch, N, K, 0, K / 64);
}

__global__ __launch_bounds__(256) void mma_gemm_sk(
    const __half* __restrict__ A, const __half* __restrict__ Bw,
    __half* __restrict__ Cp, int N, int K_total, int K_chunk) {
    const int z = blockIdx.z;
    gemm_core<0, 1, 1>(A, Bw, nullptr, Cp + (long)z * M_ROWS * D_,
                       N, K_total, (long)z * K_chunk, K_chunk / 64);
}

// ---------------------------------------------------------------------------
// Flash attention (validated R9/R11 configuration — unchanged).
// ---------------------------------------------------------------------------
constexpr int ATT_QTILE = 128 * 128;
constexpr int ATT_KTILE = 64 * 128;
constexpr int SMEM_ATT  = ATT_QTILE + 3 * ATT_KTILE;  // 40960

__global__ __launch_bounds__(128) void attention_mma(
    const __half* __restrict__ q, __half* __restrict__ o) {
    extern __shared__ char smem[];
    const uint32_t sb = smem_to_u32(smem);
    const uint32_t Qb = sb;
    const uint32_t Kst = sb + ATT_QTILE;

    const int t = threadIdx.x, lane = t & 31, wid = t >> 5;
    const int qb = blockIdx.x, h = blockIdx.y, b = blockIdx.z;
    const long rowbase = (long)b * S_ + qb * 128;
    const int colbase = h * 64;
    const float scale2 = 1.4426950408889634f * rsqrtf((float)S_);
    const __half2 s2h = __floats2half2_rn(scale2, scale2);

    {
        const __half* pq = q + (rowbase + t) * D_ + colbase;
#pragma unroll
        for (int c = 0; c < 8; c++)
            cpa16(Qb + SWZ128(t * 128 + c * 16), pq + c * 8);
    }
    const int rk = t >> 1, ck = (t & 1) * 4;
    auto loadK = [&](int kvb, int s) {
        const __half* pk = q + ((long)b * S_ + kvb * 64 + rk) * D_ + colbase;
        const uint32_t st = Kst + s * ATT_KTILE;
#pragma unroll
        for (int c = 0; c < 4; c++)
            cpa16(st + SWZ128(rk * 128 + (ck + c) * 16), pk + (ck + c) * 8);
    };
    loadK(0, 0);
    CP_COMMIT();
    loadK(1, 1);
    CP_COMMIT();

    uint32_t qf[2][4][4];
    float oacc[2][8][4];
#pragma unroll
    for (int m = 0; m < 2; m++)
#pragma unroll
        for (int i = 0; i < 8; i++)
#pragma unroll
            for (int j = 0; j < 4; j++) oacc[m][i][j] = 0.f;
    float lf[2][2] = {{0.f, 0.f}, {0.f, 0.f}};

    constexpr int NKB = S_ / 64;
    for (int kvb = 0; kvb < NKB; kvb++) {
        if (kvb + 1 < NKB) { CP_WAIT1(); } else { CP_WAIT0(); }
        __syncthreads();

        if (kvb == 0) {
#pragma unroll
            for (int mt = 0; mt < 2; mt++)
#pragma unroll
                for (int ks = 0; ks < 4; ks++) {
                    const int row = wid * 32 + mt * 16 + (lane & 15);
                    const uint32_t off = SWZ128(row * 128 + ks * 32 + (lane >> 4) * 16);
                    ldsm_x4(qf[mt][ks], Qb + off);
#pragma unroll
                    for (int i = 0; i < 4; i++) {
                        __half2 v = *(__half2*)&qf[mt][ks][i];
                        v = __hmul2(v, s2h);
                        qf[mt][ks][i] = *(uint32_t*)&v;
                    }
                }
        }
        const uint32_t Kb = Kst + (kvb % 3) * ATT_KTILE;

        float sa[2][8][4];
#pragma unroll
        for (int m = 0; m < 2; m++)
#pragma unroll
            for (int i = 0; i < 8; i++)
#pragma unroll
                for (int j = 0; j < 4; j++) sa[m][i][j] = 0.f;
#pragma unroll
        for (int ks = 0; ks < 4; ks++) {
#pragma unroll
            for (int ntp = 0; ntp < 4; ntp++) {
                const int row = ntp * 16 + ((lane >> 4) << 3) + (lane & 7);
                const uint32_t off = SWZ128(row * 128 + ks * 32 + ((lane >> 3) & 1) * 16);
                uint32_t kf[4];
                ldsm_x4(kf, Kb + off);
#pragma unroll
                for (int mt = 0; mt < 2; mt++) {
                    mma_f16(sa[mt][2 * ntp], qf[mt][ks], kf);
                    mma_f16(sa[mt][2 * ntp + 1], qf[mt][ks], kf + 2);
                }
            }
        }

        uint32_t ph[2][4][4];
#pragma unroll
        for (int m = 0; m < 2; m++) {
            __half2 h0 = __floats2half2_rn(0.f, 0.f), h1 = h0;
#pragma unroll
            for (int ks = 0; ks < 4; ks++) {
                __half2 e;
                e = h2exp2(__floats2half2_rn(sa[m][2 * ks][0], sa[m][2 * ks][1]));
                ph[m][ks][0] = *(uint32_t*)&e; h0 = __hadd2(h0, e);
                e = h2exp2(__floats2half2_rn(sa[m][2 * ks][2], sa[m][2 * ks][3]));
                ph[m][ks][1] = *(uint32_t*)&e; h1 = __hadd2(h1, e);
                e = h2exp2(__floats2half2_rn(sa[m][2 * ks + 1][0], sa[m][2 * ks + 1][1]));
                ph[m][ks][2] = *(uint32_t*)&e; h0 = __hadd2(h0, e);
                e = h2exp2(__floats2half2_rn(sa[m][2 * ks + 1][2], sa[m][2 * ks + 1][3]));
                ph[m][ks][3] = *(uint32_t*)&e; h1 = __hadd2(h1, e);
            }
            lf[m][0] += __low2float(h0) + __high2float(h0);
            lf[m][1] += __low2float(h1) + __high2float(h1);
        }

#pragma unroll
        for (int ks = 0; ks < 4; ks++) {
#pragma unroll
            for (int ntp = 0; ntp < 4; ntp++) {
                const uint32_t krow = ks * 16 + ((lane >> 3) & 1) * 8 + (lane & 7);
                const uint32_t colb = ntp * 32 + (lane >> 4) * 16;
                const uint32_t off = SWZ128(krow * 128 + colb);
                uint32_t vf[4];
                ldsm_x4t(vf, Kb + off);
#pragma unroll
                for (int mt = 0; mt < 2; mt++) {
                    mma_f16(oacc[mt][2 * ntp], ph[mt][ks], vf);
                    mma_f16(oacc[mt][2 * ntp + 1], ph[mt][ks], vf + 2);
                }
            }
        }

        if (kvb + 2 < NKB) { loadK(kvb + 2, (kvb + 2) % 3); CP_COMMIT(); }
    }

#pragma unroll
    for (int m = 0; m < 2; m++)
#pragma unroll
        for (int rg = 0; rg < 2; rg++) {
            lf[m][rg] += __shfl_xor_sync(0xffffffffu, lf[m][rg], 1);
            lf[m][rg] += __shfl_xor_sync(0xffffffffu, lf[m][rg], 2);
        }

    const int g = lane >> 2, tig = lane & 3;
#pragma unroll
    for (int mt = 0; mt < 2; mt++) {
        const float il0 = 1.f / lf[mt][0], il1 = 1.f / lf[mt][1];
#pragma unroll
        for (int nt = 0; nt < 8; nt++) {
            const long row0 = rowbase + wid * 32 + mt * 16 + g;
            const long row1 = row0 + 8;
            const int col = colbase + nt * 8 + 2 * tig;
            *(uint32_t*)&o[row0 * D_ + col] =
                packh(oacc[mt][nt][0] * il0, oacc[mt][nt][1] * il0);
            *(uint32_t*)&o[row1 * D_ + col] =
                packh(oacc[mt][nt][2] * il1, oacc[mt][nt][3] * il1);
        }
    }
}

// ---------------------------------------------------------------------------
// Prep: pure streaming fp32 -> fp16 convert (weights in native layout + x).
// Blocks: Wq [0,1024) Wo [1024,2048) W1 [2048,6144) W2 [6144,10240)
//         x [10240,11264)
// ---------------------------------------------------------------------------
__global__ __launch_bounds__(256) void prep_cvt(
    const float* __restrict__ Wq, __half* __restrict__ Tq,
    const float* __restrict__ Wo, __half* __restrict__ To,
    const float* __restrict__ W1, __half* __restrict__ T1,
    const float* __restrict__ W2, __half* __restrict__ T2,
    const float4* __restrict__ x, uint2* __restrict__ xh) {
    const int bid = blockIdx.x;
    const int t = threadIdx.x;
    if (bid >= 10240) {   // x: 1024 blocks x 256 thr x 4 float4 (strided)
        const int idx = (bid - 10240) * 256 + t;
#pragma unroll
        for (int j = 0; j < 4; j++) {
            const int k = j * 262144 + idx;
            float4 v = x[k];
            uint2 u;
            u.x = packh(v.x, v.y);
            u.y = packh(v.z, v.w);
            xh[k] = u;
        }
        return;
    }
    const float4* src; uint2* dst; long i;
    if (bid < 1024)      { src = (const float4*)Wq; dst = (uint2*)Tq; i = (long)bid * 256 + t; }
    else if (bid < 2048) { src = (const float4*)Wo; dst = (uint2*)To; i = (long)(bid - 1024) * 256 + t; }
    else if (bid < 6144) { src = (const float4*)W1; dst = (uint2*)T1; i = (long)(bid - 2048) * 256 + t; }
    else                 { src = (const float4*)W2; dst = (uint2*)T2; i = (long)(bid - 6144) * 256 + t; }
    float4 v = src[i];
    uint2 u;
    u.x = packh(v.x, v.y);
    u.y = packh(v.z, v.w);
    dst[i] = u;
}

// ---------------------------------------------------------------------------
// LN1: x1 = LN(yh + xh), fp16 in/out
// ---------------------------------------------------------------------------
__global__ __launch_bounds__(256) void ln_residual_h(
    const __half* __restrict__ a, const __half* __restrict__ res,
    const float* __restrict__ g, const float* __restrict__ be,
    __half* __restrict__ oh) {
    const int row = blockIdx.x;
    const int t = threadIdx.x;
    __shared__ float buf[D_];
    __shared__ float red[8];
    __shared__ float s_mean, s_rstd;

    float lsum = 0.f;
#pragma unroll
    for (int i = 0; i < 2; i++) {
        const int idx = (t + i * 256) * 2;
        __half2 av = *(const __half2*)&a[(long)row * D_ + idx];
        __half2 rv = *(const __half2*)&res[(long)row * D_ + idx];
        float v0 = __half2float(av.x) + __half2float(rv.x);
        float v1 = __half2float(av.y) + __half2float(rv.y);
        buf[idx] = v0; buf[idx + 1] = v1;
        lsum += v0 + v1;
    }
#pragma unroll
    for (int off = 16; off >= 1; off >>= 1)
        lsum += __shfl_xor_sync(0xffffffffu, lsum, off);
    if ((t & 31) == 0) red[t >> 5] = lsum;
    __syncthreads();
    if (t < 8) {
        float w = red[t];
#pragma unroll
        for (int off = 4; off >= 1; off >>= 1)
            w += __shfl_xor_sync(0xffu, w, off);
        if (t == 0) s_mean = w * (1.f / D_);
    }
    __syncthreads();
    const float mean = s_mean;

    float lvar = 0.f;
#pragma unroll
    for (int i = 0; i < 4; i++) {
        const int idx = t + i * 256;
        float d = buf[idx] - mean;
        lvar += d * d;
    }
#pragma unroll
    for (int off = 16; off >= 1; off >>= 1)
        lvar += __shfl_xor_sync(0xffffffffu, lvar, off);
    if ((t & 31) == 0) red[t >> 5] = lvar;
    __syncthreads();
    if (t < 8) {
        float w = red[t];
#pragma unroll
        for (int off = 4; off >= 1; off >>= 1)
            w += __shfl_xor_sync(0xffu, w, off);
        if (t == 0) s_rstd = rsqrtf(w * (1.f / D_) + EPS);
    }
    __syncthreads();
    const float rstd = s_rstd;

#pragma unroll
    for (int i = 0; i < 4; i++) {
        const int idx = t + i * 256;
        float v = (buf[idx] - mean) * rstd * g[idx] + be[idx];
        oh[(long)row * D_ + idx] = __float2half(v);
    }
}

// ---------------------------------------------------------------------------
// LN2 + 4-way split-K reduce (fp16 partials): out = LN(sum_z p[z] + b2 + x1h)
// ---------------------------------------------------------------------------
__global__ __launch_bounds__(256) void ln_reduce_final(
    const __half* __restrict__ part, const __half* __restrict__ res,
    const float* __restrict__ b2,
    const float* __restrict__ g, const float* __restrict__ be,
    float* __restrict__ out) {
    const int row = blockIdx.x;
    const int t = threadIdx.x;
    __shared__ float buf[D_];
    __shared__ float red[8];
    __shared__ float s_mean, s_rstd;
    constexpr long PS = (long)M_ROWS * D_;

    float lsum = 0.f;
#pragma unroll
    for (int i = 0; i < 2; i++) {
        const int idx = (t + i * 256) * 2;
        const long o = (long)row * D_ + idx;
        __half2 p0 = *(const __half2*)&part[o];
        __half2 p1 = *(const __half2*)&part[o + PS];
        __half2 p2 = *(const __half2*)&part[o + 2 * PS];
        __half2 p3 = *(const __half2*)&part[o + 3 * PS];
        __half2 rv = *(const __half2*)&res[o];
        float2 bv = *(const float2*)&b2[idx];
        float v0 = __half2float(p0.x) + __half2float(p1.x) + __half2float(p2.x)
                 + __half2float(p3.x) + bv.x + __half2float(rv.x);
        float v1 = __half2float(p0.y) + __half2float(p1.y) + __half2float(p2.y)
                 + __half2float(p3.y) + bv.y + __half2float(rv.y);
        buf[idx] = v0; buf[idx + 1] = v1;
        lsum += v0 + v1;
    }
#pragma unroll
    for (int off = 16; off >= 1; off >>= 1)
        lsum += __shfl_xor_sync(0xffffffffu, lsum, off);
    if ((t & 31) == 0) red[t >> 5] = lsum;
    __syncthreads();
    if (t < 8) {
        float w = red[t];
#pragma unroll
        for (int off = 4; off >= 1; off >>= 1)
            w += __shfl_xor_sync(0xffu, w, off);
        if (t == 0) s_mean = w * (1.f / D_);
    }
    __syncthreads();
    const float mean = s_mean;

    float lvar = 0.f;
#pragma unroll
    for (int i = 0; i < 4; i++) {
        const int idx = t + i * 256;
        float d = buf[idx] - mean;
        lvar += d * d;
    }
#pragma unroll
    for (int off = 16; off >= 1; off >>= 1)
        lvar += __shfl_xor_sync(0xffffffffu, lvar, off);
    if ((t & 31) == 0) red[t >> 5] = lvar;
    __syncthreads();
    if (t < 8) {
        float w = red[t];
#pragma unroll
        for (int off = 4; off >= 1; off >>= 1)
            w += __shfl_xor_sync(0xffu, w, off);
        if (t == 0) s_rstd = rsqrtf(w * (1.f / D_) + EPS);
    }
    __syncthreads();
    const float rstd = s_rstd;

#pragma unroll
    for (int i = 0; i < 4; i++) {
        const int idx = t + i * 256;
        out[(long)row * D_ + idx] = (buf[idx] - mean) * rstd * g[idx] + be[idx];
    }
}

// ---------------------------------------------------------------------------
extern "C" void kernel_launch(void* const* d_in, const int* in_sizes, int n_in,
                              void* d_out, int out_size) {
    const float* x     = (const float*)d_in[0];
    const float* Wq    = (const float*)d_in[1];
    const float* bq    = (const float*)d_in[2];
    const float* Wo    = (const float*)d_in[3];
    const float* bo    = (const float*)d_in[4];
    const float* ln1_g = (const float*)d_in[5];
    const float* ln1_b = (const float*)d_in[6];
    const float* W1    = (const float*)d_in[7];
    const float* b1    = (const float*)d_in[8];
    const float* W2    = (const float*)d_in[9];
    const float* b2    = (const float*)d_in[10];
    const float* ln2_g = (const float*)d_in[11];
    const float* ln2_b = (const float*)d_in[12];
    float* out = (float*)d_out;

    __half *xh, *qkvh, *atth, *yh, *x1h, *hh, *parth, *wq, *wo, *w1, *w2;
    cudaGetSymbolAddress((void**)&xh,    g_xh);
    cudaGetSymbolAddress((void**)&qkvh,  g_qkvh);
    cudaGetSymbolAddress((void**)&atth,  g_atth);
    cudaGetSymbolAddress((void**)&yh,    g_yh);
    cudaGetSymbolAddress((void**)&x1h,   g_x1h);
    cudaGetSymbolAddress((void**)&hh,    g_hh);
    cudaGetSymbolAddress((void**)&parth, g_parth);
    cudaGetSymbolAddress((void**)&wq,    g_wq);
    cudaGetSymbolAddress((void**)&wo,    g_wo);
    cudaGetSymbolAddress((void**)&w1,    g_w1);
    cudaGetSymbolAddress((void**)&w2,    g_w2);

    cudaFuncSetAttribute(mma_gemm<0>, cudaFuncAttributeMaxDynamicSharedMemorySize, SMEM_GEMM);
    cudaFuncSetAttribute(mma_gemm<1>, cudaFuncAttributeMaxDynamicSharedMemorySize, SMEM_GEMM);
    cudaFuncSetAttribute(mma_gemm_sk, cudaFuncAttributeMaxDynamicSharedMemorySize, SMEM_GEMM);
    cudaFuncSetAttribute(attention_mma, cudaFuncAttributeMaxDynamicSharedMemorySize, SMEM_ATT);

    dim3 thr(256);

    // Prep: streaming fp32->fp16 convert (no transpose)
    prep_cvt<<<11264, thr>>>(Wq, wq, Wo, wo, W1, w1, W2, w2,
                             (const float4*)x, (uint2*)xh);

    // 1) qkv = x @ Wq + bq
    mma_gemm<0><<<dim3(D_ / 128, M_ROWS / 128), thr, SMEM_GEMM>>>(
        xh, wq, bq, qkvh, D_, D_);

    // 2) attention
    attention_mma<<<dim3(S_ / 128, H_, B_), dim3(128), SMEM_ATT>>>(qkvh, atth);

    // 3) y = attn @ Wo + bo
    mma_gemm<0><<<dim3(D_ / 128, M_ROWS / 128), thr, SMEM_GEMM>>>(
        atth, wo, bo, yh, D_, D_);

    // 4) x1 = LN(y + x)
    ln_residual_h<<<M_ROWS, thr>>>(yh, xh, ln1_g, ln1_b, x1h);

    // 5) h = relu(x1 @ W1 + b1)
    mma_gemm<1><<<dim3(DH_ / 128, M_ROWS / 128), thr, SMEM_GEMM>>>(
        x1h, w1, b1, hh, DH_, D_);

    // 6) FFN2 split-K=4: fp16 partials = h @ W2
    mma_gemm_sk<<<dim3(D_ / 128, M_ROWS / 128, SPLITS), thr, SMEM_GEMM>>>(
        hh, w2, parth, D_, DH_, DH_ / SPLITS);

    // 7) out = LN(sum(partials) + b2 + x1)
    ln_reduce_final<<<M_ROWS, thr>>>(parth, x1h, b2, ln2_g, ln2_b, out);
}

// round 16
// speedup vs baseline: 1.0334x; 1.0334x over previous
#include <cuda_runtime.h>
#include <cuda_fp16.h>
#include <cstdint>
#include <math.h>

// Problem constants
constexpr int B_ = 2, S_ = 2048, D_ = 1024, H_ = 16, DK_ = 64, DH_ = 4096;
constexpr int M_ROWS = B_ * S_;   // 4096
constexpr float EPS = 1e-5f;
constexpr int SPLITS = 4;         // split-K factor for FFN2

// ---------------------------------------------------------------------------
// Scratch (device globals — no allocation allowed)
// Weights transposed to [N,K] fp16 (validated R14 layout).
// ---------------------------------------------------------------------------
__device__ __half g_xh[M_ROWS * D_];
__device__ __half g_qkvh[M_ROWS * D_];
__device__ __half g_atth[M_ROWS * D_];
__device__ __half g_yh[M_ROWS * D_];
__device__ __half g_x1h[M_ROWS * D_];
__device__ __half g_hh[M_ROWS * DH_];
__device__ __half g_parth[SPLITS * M_ROWS * D_];
__device__ __half g_wq[D_ * D_];
__device__ __half g_wo[D_ * D_];
__device__ __half g_w1[DH_ * D_];
__device__ __half g_w2[D_ * DH_];

// ---------------------------------------------------------------------------
// Low-level helpers
// ---------------------------------------------------------------------------
__device__ __forceinline__ uint32_t smem_to_u32(const void* p) {
    uint32_t a;
    asm("{ .reg .u64 t; cvta.to.shared.u64 t, %1; cvt.u32.u64 %0, t; }"
        : "=r"(a) : "l"(p));
    return a;
}
__device__ __forceinline__ void cpa16(uint32_t d, const void* s) {
    asm volatile("cp.async.cg.shared.global [%0], [%1], 16;" :: "r"(d), "l"(s));
}
#define CP_COMMIT() asm volatile("cp.async.commit_group;" ::: "memory")
#define CP_WAIT1()  asm volatile("cp.async.wait_group 1;" ::: "memory")
#define CP_WAIT0()  asm volatile("cp.async.wait_group 0;" ::: "memory")

__device__ __forceinline__ void ldsm_x4(uint32_t* r, uint32_t addr) {
    asm volatile("ldmatrix.sync.aligned.m8n8.x4.shared.b16 {%0,%1,%2,%3}, [%4];"
        : "=r"(r[0]), "=r"(r[1]), "=r"(r[2]), "=r"(r[3]) : "r"(addr));
}
__device__ __forceinline__ void ldsm_x4t(uint32_t* r, uint32_t addr) {
    asm volatile("ldmatrix.sync.aligned.m8n8.x4.trans.shared.b16 {%0,%1,%2,%3}, [%4];"
        : "=r"(r[0]), "=r"(r[1]), "=r"(r[2]), "=r"(r[3]) : "r"(addr));
}
__device__ __forceinline__ void mma_f16(float* c, const uint32_t* a, const uint32_t* b) {
    asm volatile(
        "mma.sync.aligned.m16n8k16.row.col.f32.f16.f16.f32 "
        "{%0,%1,%2,%3}, {%4,%5,%6,%7}, {%8,%9}, {%0,%1,%2,%3};"
        : "+f"(c[0]), "+f"(c[1]), "+f"(c[2]), "+f"(c[3])
        : "r"(a[0]), "r"(a[1]), "r"(a[2]), "r"(a[3]), "r"(b[0]), "r"(b[1]));
}

#define SWZ128(o) ((o) ^ (((o) >> 3) & 0x70))

__device__ __forceinline__ uint32_t packh(float a, float b) {
    __half2 h = __floats2half2_rn(a, b);
    return *(uint32_t*)&h;
}

// ---------------------------------------------------------------------------
// GEMM tiling constants (validated 128x128 tile, K-major B)
// ---------------------------------------------------------------------------
constexpr int TILE_B  = 16384;            // 128 rows x 64 fp16
constexpr int STAGE_B = 2 * TILE_B;
constexpr int SMEM_GEMM = 3 * STAGE_B;    // 98304

// ---------------------------------------------------------------------------
// Full-K GEMM, fp16 out (+bias, optional ReLU) — Wq, Wo, FFN1
// ---------------------------------------------------------------------------
template <int RELU>
__global__ __launch_bounds__(256) void mma_gemm(
    const __half* __restrict__ A, const __half* __restrict__ Bw,
    const float* __restrict__ bias, __half* __restrict__ Ch, int N, int K) {
    extern __shared__ char smem[];
    const uint32_t sb = smem_to_u32(smem);
    const int t = threadIdx.x, lane = t & 31, wid = t >> 5;
    const int wm = wid >> 2, wn = wid & 3;
    const int m0 = blockIdx.y * 128, n0 = blockIdx.x * 128;

    float acc[4][4][4];
#pragma unroll
    for (int i = 0; i < 4; i++)
#pragma unroll
        for (int j = 0; j < 4; j++)
#pragma unroll
            for (int k = 0; k < 4; k++) acc[i][j][k] = 0.f;

    const int r_ = t >> 1;
    const int ch_ = (t & 1) * 4;
    auto issue = [&](int kb, int s) {
        const uint32_t st = sb + s * STAGE_B;
        const long ko = (long)kb * 64;
        const __half* pa = A  + (long)(m0 + r_) * K + ko;
        const __half* pb = Bw + (long)(n0 + r_) * K + ko;
#pragma unroll
        for (int c = 0; c < 4; c++) {
            const uint32_t so = SWZ128(r_ * 128 + (ch_ + c) * 16);
            cpa16(st + so, pa + (ch_ + c) * 8);
            cpa16(st + TILE_B + so, pb + (ch_ + c) * 8);
        }
    };

    const int NB = K / 64;
    issue(0, 0); CP_COMMIT();
    issue(1, 1); CP_COMMIT();

    for (int kb = 0; kb < NB; kb++) {
        if (kb + 1 < NB) { CP_WAIT1(); } else { CP_WAIT0(); }
        __syncthreads();
        const uint32_t base = sb + (kb % 3) * STAGE_B;
        const uint32_t Ab = base, Bb = base + TILE_B;
#pragma unroll
        for (int ks = 0; ks < 4; ks++) {
            uint32_t af[4][4];
#pragma unroll
            for (int mt = 0; mt < 4; mt++) {
                const int row = wm * 64 + mt * 16 + (lane & 15);
                const uint32_t off = SWZ128(row * 128 + ks * 32 + (lane >> 4) * 16);
                ldsm_x4(af[mt], Ab + off);
            }
            uint32_t bf[2][4];
#pragma unroll
            for (int ntp = 0; ntp < 2; ntp++) {
                const int row = wn * 32 + ntp * 16 + ((lane >> 4) << 3) + (lane & 7);
                const uint32_t off = SWZ128(row * 128 + ks * 32 + ((lane >> 3) & 1) * 16);
                ldsm_x4(bf[ntp], Bb + off);
            }
#pragma unroll
            for (int mt = 0; mt < 4; mt++)
#pragma unroll
                for (int nt = 0; nt < 4; nt++)
                    mma_f16(acc[mt][nt], af[mt], &bf[nt >> 1][(nt & 1) * 2]);
        }
        if (kb + 2 < NB) { issue(kb + 2, (kb + 2) % 3); CP_COMMIT(); }
    }

    const int g = lane >> 2, tig = lane & 3;
#pragma unroll
    for (int mt = 0; mt < 4; mt++) {
#pragma unroll
        for (int nt = 0; nt < 4; nt++) {
            const int row0 = m0 + wm * 64 + mt * 16 + g;
            const int col  = n0 + wn * 32 + nt * 8 + 2 * tig;
            const float2 bv = *(const float2*)&bias[col];
            float v0 = acc[mt][nt][0] + bv.x;
            float v1 = acc[mt][nt][1] + bv.y;
            float v2 = acc[mt][nt][2] + bv.x;
            float v3 = acc[mt][nt][3] + bv.y;
            if (RELU) {
                v0 = fmaxf(v0, 0.f); v1 = fmaxf(v1, 0.f);
                v2 = fmaxf(v2, 0.f); v3 = fmaxf(v3, 0.f);
            }
            *(uint32_t*)&Ch[(long)row0 * N + col]       = packh(v0, v1);
            *(uint32_t*)&Ch[(long)(row0 + 8) * N + col] = packh(v2, v3);
        }
    }
}

// ---------------------------------------------------------------------------
// Split-K GEMM (FFN2): fp16 partials (no bias), grid.z = split.
// ---------------------------------------------------------------------------
__global__ __launch_bounds__(256) void mma_gemm_sk(
    const __half* __restrict__ A, const __half* __restrict__ Bw,
    __half* __restrict__ Cp, int N, int K_total, int K_chunk) {
    extern __shared__ char smem[];
    const uint32_t sb = smem_to_u32(smem);
    const int t = threadIdx.x, lane = t & 31, wid = t >> 5;
    const int wm = wid >> 2, wn = wid & 3;
    const int m0 = blockIdx.y * 128, n0 = blockIdx.x * 128;
    const int z = blockIdx.z;
    const long kbase = (long)z * K_chunk;
    __half* C = Cp + (long)z * M_ROWS * D_;

    float acc[4][4][4];
#pragma unroll
    for (int i = 0; i < 4; i++)
#pragma unroll
        for (int j = 0; j < 4; j++)
#pragma unroll
            for (int k = 0; k < 4; k++) acc[i][j][k] = 0.f;

    const int r_ = t >> 1;
    const int ch_ = (t & 1) * 4;
    auto issue = [&](int kb, int s) {
        const uint32_t st = sb + s * STAGE_B;
        const long ko = kbase + (long)kb * 64;
        const __half* pa = A  + (long)(m0 + r_) * K_total + ko;
        const __half* pb = Bw + (long)(n0 + r_) * K_total + ko;
#pragma unroll
        for (int c = 0; c < 4; c++) {
            const uint32_t so = SWZ128(r_ * 128 + (ch_ + c) * 16);
            cpa16(st + so, pa + (ch_ + c) * 8);
            cpa16(st + TILE_B + so, pb + (ch_ + c) * 8);
        }
    };

    const int NB = K_chunk / 64;
    issue(0, 0); CP_COMMIT();
    issue(1, 1); CP_COMMIT();

    for (int kb = 0; kb < NB; kb++) {
        if (kb + 1 < NB) { CP_WAIT1(); } else { CP_WAIT0(); }
        __syncthreads();
        const uint32_t base = sb + (kb % 3) * STAGE_B;
        const uint32_t Ab = base, Bb = base + TILE_B;
#pragma unroll
        for (int ks = 0; ks < 4; ks++) {
            uint32_t af[4][4];
#pragma unroll
            for (int mt = 0; mt < 4; mt++) {
                const int row = wm * 64 + mt * 16 + (lane & 15);
                const uint32_t off = SWZ128(row * 128 + ks * 32 + (lane >> 4) * 16);
                ldsm_x4(af[mt], Ab + off);
            }
            uint32_t bf[2][4];
#pragma unroll
            for (int ntp = 0; ntp < 2; ntp++) {
                const int row = wn * 32 + ntp * 16 + ((lane >> 4) << 3) + (lane & 7);
                const uint32_t off = SWZ128(row * 128 + ks * 32 + ((lane >> 3) & 1) * 16);
                ldsm_x4(bf[ntp], Bb + off);
            }
#pragma unroll
            for (int mt = 0; mt < 4; mt++)
#pragma unroll
                for (int nt = 0; nt < 4; nt++)
                    mma_f16(acc[mt][nt], af[mt], &bf[nt >> 1][(nt & 1) * 2]);
        }
        if (kb + 2 < NB) { issue(kb + 2, (kb + 2) % 3); CP_COMMIT(); }
    }

    const int g = lane >> 2, tig = lane & 3;
#pragma unroll
    for (int mt = 0; mt < 4; mt++) {
#pragma unroll
        for (int nt = 0; nt < 4; nt++) {
            const int row0 = m0 + wm * 64 + mt * 16 + g;
            const int col  = n0 + wn * 32 + nt * 8 + 2 * tig;
            *(uint32_t*)&C[(long)row0 * N + col] =
                packh(acc[mt][nt][0], acc[mt][nt][1]);
            *(uint32_t*)&C[(long)(row0 + 8) * N + col] =
                packh(acc[mt][nt][2], acc[mt][nt][3]);
        }
    }
}

// ---------------------------------------------------------------------------
// Flash attention (validated R9/R11 configuration).
// ---------------------------------------------------------------------------
constexpr int ATT_QTILE = 128 * 128;
constexpr int ATT_KTILE = 64 * 128;
constexpr int SMEM_ATT  = ATT_QTILE + 3 * ATT_KTILE;  // 40960

__global__ __launch_bounds__(128) void attention_mma(
    const __half* __restrict__ q, __half* __restrict__ o) {
    extern __shared__ char smem[];
    const uint32_t sb = smem_to_u32(smem);
    const uint32_t Qb = sb;
    const uint32_t Kst = sb + ATT_QTILE;

    const int t = threadIdx.x, lane = t & 31, wid = t >> 5;
    const int qb = blockIdx.x, h = blockIdx.y, b = blockIdx.z;
    const long rowbase = (long)b * S_ + qb * 128;
    const int colbase = h * 64;
    const float scale2 = 1.4426950408889634f * rsqrtf((float)S_);
    const __half2 s2h = __floats2half2_rn(scale2, scale2);

    {
        const __half* pq = q + (rowbase + t) * D_ + colbase;
#pragma unroll
        for (int c = 0; c < 8; c++)
            cpa16(Qb + SWZ128(t * 128 + c * 16), pq + c * 8);
    }
    const int rk = t >> 1, ck = (t & 1) * 4;
    auto loadK = [&](int kvb, int s) {
        const __half* pk = q + ((long)b * S_ + kvb * 64 + rk) * D_ + colbase;
        const uint32_t st = Kst + s * ATT_KTILE;
#pragma unroll
        for (int c = 0; c < 4; c++)
            cpa16(st + SWZ128(rk * 128 + (ck + c) * 16), pk + (ck + c) * 8);
    };
    loadK(0, 0);
    CP_COMMIT();
    loadK(1, 1);
    CP_COMMIT();

    uint32_t qf[2][4][4];
    float oacc[2][8][4];
#pragma unroll
    for (int m = 0; m < 2; m++)
#pragma unroll
        for (int i = 0; i < 8; i++)
#pragma unroll
            for (int j = 0; j < 4; j++) oacc[m][i][j] = 0.f;
    float lf[2][2] = {{0.f, 0.f}, {0.f, 0.f}};

    constexpr int NKB = S_ / 64;
    for (int kvb = 0; kvb < NKB; kvb++) {
        if (kvb + 1 < NKB) { CP_WAIT1(); } else { CP_WAIT0(); }
        __syncthreads();

        if (kvb == 0) {
#pragma unroll
            for (int mt = 0; mt < 2; mt++)
#pragma unroll
                for (int ks = 0; ks < 4; ks++) {
                    const int row = wid * 32 + mt * 16 + (lane & 15);
                    const uint32_t off = SWZ128(row * 128 + ks * 32 + (lane >> 4) * 16);
                    ldsm_x4(qf[mt][ks], Qb + off);
#pragma unroll
                    for (int i = 0; i < 4; i++) {
                        __half2 v = *(__half2*)&qf[mt][ks][i];
                        v = __hmul2(v, s2h);
                        qf[mt][ks][i] = *(uint32_t*)&v;
                    }
                }
        }
        const uint32_t Kb = Kst + (kvb % 3) * ATT_KTILE;

        float sa[2][8][4];
#pragma unroll
        for (int m = 0; m < 2; m++)
#pragma unroll
            for (int i = 0; i < 8; i++)
#pragma unroll
                for (int j = 0; j < 4; j++) sa[m][i][j] = 0.f;
#pragma unroll
        for (int ks = 0; ks < 4; ks++) {
#pragma unroll
            for (int ntp = 0; ntp < 4; ntp++) {
                const int row = ntp * 16 + ((lane >> 4) << 3) + (lane & 7);
                const uint32_t off = SWZ128(row * 128 + ks * 32 + ((lane >> 3) & 1) * 16);
                uint32_t kf[4];
                ldsm_x4(kf, Kb + off);
#pragma unroll
                for (int mt = 0; mt < 2; mt++) {
                    mma_f16(sa[mt][2 * ntp], qf[mt][ks], kf);
                    mma_f16(sa[mt][2 * ntp + 1], qf[mt][ks], kf + 2);
                }
            }
        }

        uint32_t ph[2][4][4];
#pragma unroll
        for (int m = 0; m < 2; m++) {
            __half2 h0 = __floats2half2_rn(0.f, 0.f), h1 = h0;
#pragma unroll
            for (int ks = 0; ks < 4; ks++) {
                __half2 e;
                e = h2exp2(__floats2half2_rn(sa[m][2 * ks][0], sa[m][2 * ks][1]));
                ph[m][ks][0] = *(uint32_t*)&e; h0 = __hadd2(h0, e);
                e = h2exp2(__floats2half2_rn(sa[m][2 * ks][2], sa[m][2 * ks][3]));
                ph[m][ks][1] = *(uint32_t*)&e; h1 = __hadd2(h1, e);
                e = h2exp2(__floats2half2_rn(sa[m][2 * ks + 1][0], sa[m][2 * ks + 1][1]));
                ph[m][ks][2] = *(uint32_t*)&e; h0 = __hadd2(h0, e);
                e = h2exp2(__floats2half2_rn(sa[m][2 * ks + 1][2], sa[m][2 * ks + 1][3]));
                ph[m][ks][3] = *(uint32_t*)&e; h1 = __hadd2(h1, e);
            }
            lf[m][0] += __low2float(h0) + __high2float(h0);
            lf[m][1] += __low2float(h1) + __high2float(h1);
        }

#pragma unroll
        for (int ks = 0; ks < 4; ks++) {
#pragma unroll
            for (int ntp = 0; ntp < 4; ntp++) {
                const uint32_t krow = ks * 16 + ((lane >> 3) & 1) * 8 + (lane & 7);
                const uint32_t colb = ntp * 32 + (lane >> 4) * 16;
                const uint32_t off = SWZ128(krow * 128 + colb);
                uint32_t vf[4];
                ldsm_x4t(vf, Kb + off);
#pragma unroll
                for (int mt = 0; mt < 2; mt++) {
                    mma_f16(oacc[mt][2 * ntp], ph[mt][ks], vf);
                    mma_f16(oacc[mt][2 * ntp + 1], ph[mt][ks], vf + 2);
                }
            }
        }

        if (kvb + 2 < NKB) { loadK(kvb + 2, (kvb + 2) % 3); CP_COMMIT(); }
    }

#pragma unroll
    for (int m = 0; m < 2; m++)
#pragma unroll
        for (int rg = 0; rg < 2; rg++) {
            lf[m][rg] += __shfl_xor_sync(0xffffffffu, lf[m][rg], 1);
            lf[m][rg] += __shfl_xor_sync(0xffffffffu, lf[m][rg], 2);
        }

    const int g = lane >> 2, tig = lane & 3;
#pragma unroll
    for (int mt = 0; mt < 2; mt++) {
        const float il0 = 1.f / lf[mt][0], il1 = 1.f / lf[mt][1];
#pragma unroll
        for (int nt = 0; nt < 8; nt++) {
            const long row0 = rowbase + wid * 32 + mt * 16 + g;
            const long row1 = row0 + 8;
            const int col = colbase + nt * 8 + 2 * tig;
            *(uint32_t*)&o[row0 * D_ + col] =
                packh(oacc[mt][nt][0] * il0, oacc[mt][nt][1] * il0);
            *(uint32_t*)&o[row1 * D_ + col] =
                packh(oacc[mt][nt][2] * il1, oacc[mt][nt][3] * il1);
        }
    }
}

// ---------------------------------------------------------------------------
// Prep: fast transpose (64k x 32n tiles, half2 stores = 128B/warp) + x cvt.
// Blocks: Wq [0,512) Wo [512,1024) W1 [1024,3072) W2 [3072,5120)
//         x [5120,6144)
// ---------------------------------------------------------------------------
__global__ __launch_bounds__(256) void prep_all(
    const float* __restrict__ Wq, __half* __restrict__ Tq,
    const float* __restrict__ Wo, __half* __restrict__ To,
    const float* __restrict__ W1, __half* __restrict__ T1,
    const float* __restrict__ W2, __half* __restrict__ T2,
    const float4* __restrict__ x, uint2* __restrict__ xh) {
    const int bid = blockIdx.x;
    const int t = threadIdx.x;
    if (bid >= 5120) {   // x convert: 1024 blocks x 256 thr x 4 float4
        const int idx = (bid - 5120) * 256 + t;
#pragma unroll
        for (int j = 0; j < 4; j++) {
            const int k = j * 262144 + idx;
            float4 v = x[k];
            uint2 u;
            u.x = packh(v.x, v.y);
            u.y = packh(v.z, v.w);
            xh[k] = u;
        }
        return;
    }
    const float* W; __half* T; int K, N, tb;
    if (bid < 512)       { W = Wq; T = Tq; K = D_;  N = D_;  tb = bid; }
    else if (bid < 1024) { W = Wo; T = To; K = D_;  N = D_;  tb = bid - 512; }
    else if (bid < 3072) { W = W1; T = T1; K = D_;  N = DH_; tb = bid - 1024; }
    else                 { W = W2; T = T2; K = DH_; N = D_;  tb = bid - 3072; }
    const int ntiles = N / 32;
    const int n0 = (tb % ntiles) * 32, k0 = (tb / ntiles) * 64;

    __shared__ float tile[64][33];
    // Load 64(k) x 32(n): warp reads 32 consecutive n (128B); 8 k-rows/pass.
    const int lr = t >> 5, lc = t & 31;
#pragma unroll
    for (int i = 0; i < 8; i++)
        tile[lr + i * 8][lc] = W[(long)(k0 + lr + i * 8) * N + n0 + lc];
    __syncthreads();
    // Store: each thread writes half2 (2 consecutive k); warp covers 64 k =
    // 128B contiguous per n-row. 32 n-rows in 4 passes of 8.
    const int kk = t & 31, nn = t >> 5;
#pragma unroll
    for (int i = 0; i < 4; i++) {
        const int n = nn + i * 8;
        __half2 v = __floats2half2_rn(tile[2 * kk][n], tile[2 * kk + 1][n]);
        *(__half2*)&T[(long)(n0 + n) * K + k0 + 2 * kk] = v;
    }
}

// ---------------------------------------------------------------------------
// LN1: x1 = LN(yh + xh), fp16 in/out
// ---------------------------------------------------------------------------
__global__ __launch_bounds__(256) void ln_residual_h(
    const __half* __restrict__ a, const __half* __restrict__ res,
    const float* __restrict__ g, const float* __restrict__ be,
    __half* __restrict__ oh) {
    const int row = blockIdx.x;
    const int t = threadIdx.x;
    __shared__ float buf[D_];
    __shared__ float red[8];
    __shared__ float s_mean, s_rstd;

    float lsum = 0.f;
#pragma unroll
    for (int i = 0; i < 2; i++) {
        const int idx = (t + i * 256) * 2;
        __half2 av = *(const __half2*)&a[(long)row * D_ + idx];
        __half2 rv = *(const __half2*)&res[(long)row * D_ + idx];
        float v0 = __half2float(av.x) + __half2float(rv.x);
        float v1 = __half2float(av.y) + __half2float(rv.y);
        buf[idx] = v0; buf[idx + 1] = v1;
        lsum += v0 + v1;
    }
#pragma unroll
    for (int off = 16; off >= 1; off >>= 1)
        lsum += __shfl_xor_sync(0xffffffffu, lsum, off);
    if ((t & 31) == 0) red[t >> 5] = lsum;
    __syncthreads();
    if (t < 8) {
        float w = red[t];
#pragma unroll
        for (int off = 4; off >= 1; off >>= 1)
            w += __shfl_xor_sync(0xffu, w, off);
        if (t == 0) s_mean = w * (1.f / D_);
    }
    __syncthreads();
    const float mean = s_mean;

    float lvar = 0.f;
#pragma unroll
    for (int i = 0; i < 4; i++) {
        const int idx = t + i * 256;
        float d = buf[idx] - mean;
        lvar += d * d;
    }
#pragma unroll
    for (int off = 16; off >= 1; off >>= 1)
        lvar += __shfl_xor_sync(0xffffffffu, lvar, off);
    if ((t & 31) == 0) red[t >> 5] = lvar;
    __syncthreads();
    if (t < 8) {
        float w = red[t];
#pragma unroll
        for (int off = 4; off >= 1; off >>= 1)
            w += __shfl_xor_sync(0xffu, w, off);
        if (t == 0) s_rstd = rsqrtf(w * (1.f / D_) + EPS);
    }
    __syncthreads();
    const float rstd = s_rstd;

#pragma unroll
    for (int i = 0; i < 4; i++) {
        const int idx = t + i * 256;
        float v = (buf[idx] - mean) * rstd * g[idx] + be[idx];
        oh[(long)row * D_ + idx] = __float2half(v);
    }
}

// ---------------------------------------------------------------------------
// LN2 + 4-way split-K reduce (fp16 partials): out = LN(sum_z p[z] + b2 + x1h)
// ---------------------------------------------------------------------------
__global__ __launch_bounds__(256) void ln_reduce_final(
    const __half* __restrict__ part, const __half* __restrict__ res,
    const float* __restrict__ b2,
    const float* __restrict__ g, const float* __restrict__ be,
    float* __restrict__ out) {
    const int row = blockIdx.x;
    const int t = threadIdx.x;
    __shared__ float buf[D_];
    __shared__ float red[8];
    __shared__ float s_mean, s_rstd;
    constexpr long PS = (long)M_ROWS * D_;

    float lsum = 0.f;
#pragma unroll
    for (int i = 0; i < 2; i++) {
        const int idx = (t + i * 256) * 2;
        const long o = (long)row * D_ + idx;
        __half2 p0 = *(const __half2*)&part[o];
        __half2 p1 = *(const __half2*)&part[o + PS];
        __half2 p2 = *(const __half2*)&part[o + 2 * PS];
        __half2 p3 = *(const __half2*)&part[o + 3 * PS];
        __half2 rv = *(const __half2*)&res[o];
        float2 bv = *(const float2*)&b2[idx];
        float v0 = __half2float(p0.x) + __half2float(p1.x) + __half2float(p2.x)
                 + __half2float(p3.x) + bv.x + __half2float(rv.x);
        float v1 = __half2float(p0.y) + __half2float(p1.y) + __half2float(p2.y)
                 + __half2float(p3.y) + bv.y + __half2float(rv.y);
        buf[idx] = v0; buf[idx + 1] = v1;
        lsum += v0 + v1;
    }
#pragma unroll
    for (int off = 16; off >= 1; off >>= 1)
        lsum += __shfl_xor_sync(0xffffffffu, lsum, off);
    if ((t & 31) == 0) red[t >> 5] = lsum;
    __syncthreads();
    if (t < 8) {
        float w = red[t];
#pragma unroll
        for (int off = 4; off >= 1; off >>= 1)
            w += __shfl_xor_sync(0xffu, w, off);
        if (t == 0) s_mean = w * (1.f / D_);
    }
    __syncthreads();
    const float mean = s_mean;

    float lvar = 0.f;
#pragma unroll
    for (int i = 0; i < 4; i++) {
        const int idx = t + i * 256;
        float d = buf[idx] - mean;
        lvar += d * d;
    }
#pragma unroll
    for (int off = 16; off >= 1; off >>= 1)
        lvar += __shfl_xor_sync(0xffffffffu, lvar, off);
    if ((t & 31) == 0) red[t >> 5] = lvar;
    __syncthreads();
    if (t < 8) {
        float w = red[t];
#pragma unroll
        for (int off = 4; off >= 1; off >>= 1)
            w += __shfl_xor_sync(0xffu, w, off);
        if (t == 0) s_rstd = rsqrtf(w * (1.f / D_) + EPS);
    }
    __syncthreads();
    const float rstd = s_rstd;

#pragma unroll
    for (int i = 0; i < 4; i++) {
        const int idx = t + i * 256;
        out[(long)row * D_ + idx] = (buf[idx] - mean) * rstd * g[idx] + be[idx];
    }
}

// ---------------------------------------------------------------------------
extern "C" void kernel_launch(void* const* d_in, const int* in_sizes, int n_in,
                              void* d_out, int out_size) {
    const float* x     = (const float*)d_in[0];
    const float* Wq    = (const float*)d_in[1];
    const float* bq    = (const float*)d_in[2];
    const float* Wo    = (const float*)d_in[3];
    const float* bo    = (const float*)d_in[4];
    const float* ln1_g = (const float*)d_in[5];
    const float* ln1_b = (const float*)d_in[6];
    const float* W1    = (const float*)d_in[7];
    const float* b1    = (const float*)d_in[8];
    const float* W2    = (const float*)d_in[9];
    const float* b2    = (const float*)d_in[10];
    const float* ln2_g = (const float*)d_in[11];
    const float* ln2_b = (const float*)d_in[12];
    float* out = (float*)d_out;

    __half *xh, *qkvh, *atth, *yh, *x1h, *hh, *parth, *wq, *wo, *w1, *w2;
    cudaGetSymbolAddress((void**)&xh,    g_xh);
    cudaGetSymbolAddress((void**)&qkvh,  g_qkvh);
    cudaGetSymbolAddress((void**)&atth,  g_atth);
    cudaGetSymbolAddress((void**)&yh,    g_yh);
    cudaGetSymbolAddress((void**)&x1h,   g_x1h);
    cudaGetSymbolAddress((void**)&hh,    g_hh);
    cudaGetSymbolAddress((void**)&parth, g_parth);
    cudaGetSymbolAddress((void**)&wq,    g_wq);
    cudaGetSymbolAddress((void**)&wo,    g_wo);
    cudaGetSymbolAddress((void**)&w1,    g_w1);
    cudaGetSymbolAddress((void**)&w2,    g_w2);

    cudaFuncSetAttribute(mma_gemm<0>, cudaFuncAttributeMaxDynamicSharedMemorySize, SMEM_GEMM);
    cudaFuncSetAttribute(mma_gemm<1>, cudaFuncAttributeMaxDynamicSharedMemorySize, SMEM_GEMM);
    cudaFuncSetAttribute(mma_gemm_sk, cudaFuncAttributeMaxDynamicSharedMemorySize, SMEM_GEMM);
    cudaFuncSetAttribute(attention_mma, cudaFuncAttributeMaxDynamicSharedMemorySize, SMEM_ATT);

    dim3 thr(256);

    // Prep: fast transpose + x convert (one launch)
    prep_all<<<6144, thr>>>(Wq, wq, Wo, wo, W1, w1, W2, w2,
                            (const float4*)x, (uint2*)xh);

    // 1) qkv = x @ Wq + bq
    mma_gemm<0><<<dim3(D_ / 128, M_ROWS / 128), thr, SMEM_GEMM>>>(
        xh, wq, bq, qkvh, D_, D_);

    // 2) attention
    attention_mma<<<dim3(S_ / 128, H_, B_), dim3(128), SMEM_ATT>>>(qkvh, atth);

    // 3) y = attn @ Wo + bo (fp16)
    mma_gemm<0><<<dim3(D_ / 128, M_ROWS / 128), thr, SMEM_GEMM>>>(
        atth, wo, bo, yh, D_, D_);

    // 4) x1 = LN(y + x) (fp16)
    ln_residual_h<<<M_ROWS, thr>>>(yh, xh, ln1_g, ln1_b, x1h);

    // 5) h = relu(x1 @ W1 + b1) (fp16)
    mma_gemm<1><<<dim3(DH_ / 128, M_ROWS / 128), thr, SMEM_GEMM>>>(
        x1h, w1, b1, hh, DH_, D_);

    // 6) FFN2 split-K=4: fp16 partials = h @ W2
    mma_gemm_sk<<<dim3(D_ / 128, M_ROWS / 128, SPLITS), thr, SMEM_GEMM>>>(
        hh, w2, parth, D_, DH_, DH_ / SPLITS);

    // 7) out = LN(sum(partials) + b2 + x1) (fp32)
    ln_reduce_final<<<M_ROWS, thr>>>(parth, x1h, b2, ln2_g, ln2_b, out);
}